// round 16
// baseline (speedup 1.0000x reference)
#include <cuda_runtime.h>
#include <cstdint>

#define BB 4
#define NN 2048
#define HH 12
#define DD 64
#define CC 768
#define QKVW 2304

// ---- scratch (device globals: no allocations allowed) ----
__device__ float g_qkv[(size_t)BB*NN*QKVW];   // [B*N, 3*C] raw f32
__device__ float g_attn[(size_t)BB*NN*HH*DD]; // [B,N,H,D], tf32-rounded bits
__device__ float g_wT[(size_t)QKVW*CC];       // W^T [N][K], tf32-rounded bits
__device__ float g_xtf[(size_t)BB*NN*CC];     // x, tf32-rounded bits
__device__ unsigned char g_mask[BB*NN];

// ---- helpers ----
__device__ __forceinline__ uint32_t f2tf(float f) {
    uint32_t u;
    asm("cvt.rna.tf32.f32 %0, %1;" : "=r"(u) : "f"(f));
    return u;
}
__device__ __forceinline__ void mma8(float* c, const uint32_t* a, const uint32_t* b) {
    asm volatile(
        "mma.sync.aligned.m16n8k8.row.col.f32.tf32.tf32.f32 "
        "{%0,%1,%2,%3},{%4,%5,%6,%7},{%8,%9},{%0,%1,%2,%3};"
        : "+f"(c[0]), "+f"(c[1]), "+f"(c[2]), "+f"(c[3])
        : "r"(a[0]), "r"(a[1]), "r"(a[2]), "r"(a[3]), "r"(b[0]), "r"(b[1]));
}
__device__ __forceinline__ void cpa16(void* smem, const void* g) {
    uint32_t s = (uint32_t)__cvta_generic_to_shared(smem);
    asm volatile("cp.async.cg.shared.global [%0], [%1], 16;" :: "r"(s), "l"(g));
}
#define CP_COMMIT() asm volatile("cp.async.commit_group;")
#define CP_WAIT(n)  asm volatile("cp.async.wait_group %0;" :: "n"(n))

// ============================================================
// Mask canonicalization (dtype-robust, deterministic).
// ============================================================
__global__ void mask_conv_kernel(const void* __restrict__ mraw)
{
    __shared__ int s_not_word;
    const int tid = threadIdx.x;
    if (tid == 0) s_not_word = 0;
    __syncthreads();

    const unsigned int* w = (const unsigned int*)mraw;
    for (int i = tid; i < 2048; i += blockDim.x) {
        unsigned int v = w[i];
        if (v != 0u && v != 1u && v != 0x3F800000u) atomicOr(&s_not_word, 1);
    }
    __syncthreads();

    const int wordlike = !s_not_word;
    const unsigned char* bptr = (const unsigned char*)mraw;
    for (int i = tid; i < BB * NN; i += blockDim.x) {
        unsigned char r;
        if (wordlike) r = (unsigned char)(w[i] != 0u);
        else          r = (unsigned char)(bptr[i] != 0);
        g_mask[i] = r;
    }
}

// ============================================================
// x -> tf32-rounded copy
// ============================================================
__global__ void conv_x_kernel(const float* __restrict__ x)
{
    size_t i = ((size_t)blockIdx.x * 256 + threadIdx.x) * 4;
    float4 v = *(const float4*)(x + i);
    *(uint4*)&g_xtf[i] = make_uint4(f2tf(v.x), f2tf(v.y), f2tf(v.z), f2tf(v.w));
}

// ============================================================
// Tiled transpose with tf32 rounding: g_wT[c][r] = tf32(in[r][c])
// ============================================================
__global__ void transpose_k(const float* __restrict__ in, int R, int C)
{
    __shared__ float t[32][33];
    int c0 = blockIdx.x * 32, r0 = blockIdx.y * 32;
    int x = threadIdx.x, y = threadIdx.y;    // 32 x 8
    #pragma unroll
    for (int i = 0; i < 32; i += 8)
        t[y + i][x] = in[(size_t)(r0 + y + i) * C + c0 + x];
    __syncthreads();
    #pragma unroll
    for (int i = 0; i < 32; i += 8)
        g_wT[(size_t)(c0 + y + i) * R + r0 + x] = __uint_as_float(f2tf(t[x][y + i]));
}

// ============================================================
// tf32 GEMM, 3-stage cp.async pipeline, 32-k chunks,
// 1 barrier per chunk (64 MMAs/warp between barriers).
// MODE 0: A = g_xtf,  C -> g_qkv (+bias)
// MODE 1: A = g_attn, C -> Cout  (+bias)
// ============================================================
#define SP 36                                  // stride: 4*lr+lq distinct mod 32
#define GCH 32                                 // k per chunk
#define G_STAGE (128 * SP * 2)                 // A + B floats per stage
#define GEMM_SM_BYTES (3 * G_STAGE * 4)        // 110,592 -> 2 CTAs/SM

template<int MODE>
__global__ __launch_bounds__(256) void gemm_tc(
    const float* __restrict__ bias, float* __restrict__ Cout, int K, int Nn)
{
    extern __shared__ float gs[];
    const int tid = threadIdx.x, lane = tid & 31, w = tid >> 5;
    const int wm = w >> 2, wn = w & 3;
    const int lr = lane >> 2, lq = lane & 3;
    const int bm = blockIdx.y * 128, bn = blockIdx.x * 128;
    const float* Ap = (MODE == 1) ? g_attn : g_xtf;
    float* Cp = (MODE == 0) ? g_qkv : Cout;
    const int nch = K / GCH;

    const int row = tid >> 1, kq = (tid & 1) * 16;

    float acc[4][4][4];
    #pragma unroll
    for (int i = 0; i < 4; i++)
        #pragma unroll
        for (int j = 0; j < 4; j++)
            #pragma unroll
            for (int e = 0; e < 4; e++) acc[i][j][e] = 0.f;

    #define G_ISSUE(c) do { \
        float* st = gs + ((c) % 3) * G_STAGE; \
        const float* ga = Ap + (size_t)(bm + row) * K + (c) * GCH + kq; \
        cpa16(st + row * SP + kq,      ga); \
        cpa16(st + row * SP + kq + 4,  ga + 4); \
        cpa16(st + row * SP + kq + 8,  ga + 8); \
        cpa16(st + row * SP + kq + 12, ga + 12); \
        const float* gb = g_wT + (size_t)(bn + row) * K + (c) * GCH + kq; \
        cpa16(st + 128 * SP + row * SP + kq,      gb); \
        cpa16(st + 128 * SP + row * SP + kq + 4,  gb + 4); \
        cpa16(st + 128 * SP + row * SP + kq + 8,  gb + 8); \
        cpa16(st + 128 * SP + row * SP + kq + 12, gb + 12); \
        CP_COMMIT(); \
    } while (0)

    G_ISSUE(0);
    G_ISSUE(1);

    for (int c = 0; c < nch; c++) {
        if (c + 1 < nch) { CP_WAIT(1); } else { CP_WAIT(0); }
        __syncthreads();
        const uint32_t* As = (const uint32_t*)(gs + (c % 3) * G_STAGE);
        const uint32_t* Bs = As + 128 * SP;
        #pragma unroll
        for (int ks = 0; ks < GCH; ks += 8) {
            uint32_t a[4][4], bb[4][2];
            #pragma unroll
            for (int mf = 0; mf < 4; mf++) {
                int r = wm * 64 + mf * 16;
                a[mf][0] = As[(r + lr    ) * SP + ks + lq];
                a[mf][1] = As[(r + lr + 8) * SP + ks + lq];
                a[mf][2] = As[(r + lr    ) * SP + ks + lq + 4];
                a[mf][3] = As[(r + lr + 8) * SP + ks + lq + 4];
            }
            #pragma unroll
            for (int nf = 0; nf < 4; nf++) {
                int cdx = wn * 32 + nf * 8;
                bb[nf][0] = Bs[(cdx + lr) * SP + ks + lq];
                bb[nf][1] = Bs[(cdx + lr) * SP + ks + lq + 4];
            }
            #pragma unroll
            for (int mf = 0; mf < 4; mf++)
                #pragma unroll
                for (int nf = 0; nf < 4; nf++)
                    mma8(acc[mf][nf], a[mf], bb[nf]);
        }
        if (c + 2 < nch) G_ISSUE(c + 2);
    }

    // epilogue: coalesced float2 + bias
    #pragma unroll
    for (int mf = 0; mf < 4; mf++) {
        int rr0 = bm + wm * 64 + mf * 16 + lr;
        #pragma unroll
        for (int nf = 0; nf < 4; nf++) {
            int cc = bn + wn * 32 + nf * 8 + 2 * lq;
            float bx = bias[cc], by = bias[cc + 1];
            *(float2*)&Cp[(size_t)rr0 * Nn + cc] =
                make_float2(acc[mf][nf][0] + bx, acc[mf][nf][1] + by);
            *(float2*)&Cp[(size_t)(rr0 + 8) * Nn + cc] =
                make_float2(acc[mf][nf][2] + bx, acc[mf][nf][3] + by);
        }
    }
}

// ============================================================
// Fused flash attention, tf32 MMA, register-resident softmax.
// 512 threads (16 warps), 128q x 64k tiles, warp grid 4x4
// (per-warp tile 32q x 16k — identical fragment code to R15).
// K and V double-buffered cp.async. 3 barriers per tile.
// ============================================================
#define SK 68
#define SV 72
#define SS 68
#define ATT_SM_FLOATS (128*SK + 2*64*SK + 2*64*SV + 128*SS + 128*8)
#define ATT_SM_BYTES  (ATT_SM_FLOATS * 4)   // 145,408 -> 1 CTA/SM

__global__ __launch_bounds__(512, 1) void attn_kernel(
    const float* __restrict__ alibi)
{
    extern __shared__ float sm[];
    uint32_t* Qs = (uint32_t*)sm;           // [128][SK] tf32, pre-scaled
    float* Kf   = sm + 128 * SK;            // [2][64][SK] raw f32
    float* Vf   = Kf + 2 * 64 * SK;         // [2][64][SV] raw f32
    float* Ss   = Vf + 2 * 64 * SV;         // [128][SS] tf32 prob bits
    float* red  = Ss + 128 * SS;            // [128][8]: max[0..3], sum[4..7]

    const int tid = threadIdx.x, lane = tid & 31, w = tid >> 5;
    const int wm = w >> 2, wn = w & 3;      // 4 x 4
    const int lr = lane >> 2, lq = lane & 3;
    const int qt = blockIdx.x, h = blockIdx.y, b = blockIdx.z;
    const int q0 = qt * 128;
    const int rm = wm * 32, cn = wn * 16;

    const int qldr = tid >> 4;              // 0..31 (Q loader)
    const int qldc = (tid & 15) * 4;
    const int kldr = tid >> 3;              // 0..63 (K/V loader)
    const int kldc = (tid & 7) * 8;

    const float* Qg = g_qkv + (size_t)(b * NN + q0) * QKVW + h * 64;
    const float* Kbase = g_qkv + (size_t)(b * NN) * QKVW + CC + h * 64;
    const float* Vbase = g_qkv + (size_t)(b * NN) * QKVW + 2 * CC + h * 64;

    // ---- load Q (scale + tf32): 128 x 64 ----
    #pragma unroll
    for (int it = 0; it < 4; it++) {
        int row = qldr + it * 32;
        float4 v = *(const float4*)(Qg + (size_t)row * QKVW + qldc);
        *(uint4*)&Qs[row * SK + qldc] =
            make_uint4(f2tf(v.x * 0.125f), f2tf(v.y * 0.125f),
                       f2tf(v.z * 0.125f), f2tf(v.w * 0.125f));
    }

    // ---- prefetch K(0), V(0) (separate groups) ----
    cpa16(&Kf[kldr * SK + kldc],     Kbase + (size_t)kldr * QKVW + kldc);
    cpa16(&Kf[kldr * SK + kldc + 4], Kbase + (size_t)kldr * QKVW + kldc + 4);
    CP_COMMIT();
    cpa16(&Vf[kldr * SV + kldc],     Vbase + (size_t)kldr * QKVW + kldc);
    cpa16(&Vf[kldr * SV + kldc + 4], Vbase + (size_t)kldr * QKVW + kldc + 4);
    CP_COMMIT();

    float oacc[2][2][4];
    #pragma unroll
    for (int i = 0; i < 2; i++)
        #pragma unroll
        for (int j = 0; j < 2; j++)
            #pragma unroll
            for (int e = 0; e < 4; e++) oacc[i][j][e] = 0.f;
    float mrow_r[2][2] = {{-1e30f, -1e30f}, {-1e30f, -1e30f}};
    float lrow_r[2][2] = {{0.f, 0.f}, {0.f, 0.f}};

    const size_t abase = ((size_t)(b * HH + h) * NN + q0) * NN;

    for (int kt = 0; kt < 32; kt++) {
        const int kc0 = kt * 64;
        CP_WAIT(1);        // K(kt) landed (V(kt) may be pending)
        __syncthreads();   // S1: K visible; prev PV reads done

        // alibi + mask to regs
        float2 al[2][2][2];
        unsigned short mk[2];
        #pragma unroll
        for (int mf = 0; mf < 2; mf++) {
            int q = rm + mf * 16 + lr;
            #pragma unroll
            for (int nf = 0; nf < 2; nf++) {
                int c = cn + nf * 8 + 2 * lq;
                al[mf][nf][0] = *(const float2*)(alibi + abase + (size_t)q * NN + kc0 + c);
                al[mf][nf][1] = *(const float2*)(alibi + abase + (size_t)(q + 8) * NN + kc0 + c);
            }
        }
        #pragma unroll
        for (int nf = 0; nf < 2; nf++)
            mk[nf] = *(const unsigned short*)&g_mask[b * NN + kc0 + cn + nf * 8 + 2 * lq];

        // ---- S = Q @ K^T ----
        const float* Kb = Kf + (kt & 1) * 64 * SK;
        float sacc[2][2][4];
        #pragma unroll
        for (int i = 0; i < 2; i++)
            #pragma unroll
            for (int j = 0; j < 2; j++)
                #pragma unroll
                for (int e = 0; e < 4; e++) sacc[i][j][e] = 0.f;

        #pragma unroll
        for (int kc = 0; kc < 64; kc += 8) {
            uint32_t a[2][4], bf[2][2];
            #pragma unroll
            for (int mf = 0; mf < 2; mf++) {
                int r = rm + mf * 16;
                a[mf][0] = Qs[(r + lr    ) * SK + kc + lq];
                a[mf][1] = Qs[(r + lr + 8) * SK + kc + lq];
                a[mf][2] = Qs[(r + lr    ) * SK + kc + lq + 4];
                a[mf][3] = Qs[(r + lr + 8) * SK + kc + lq + 4];
            }
            #pragma unroll
            for (int nf = 0; nf < 2; nf++) {
                int c = cn + nf * 8;
                bf[nf][0] = f2tf(Kb[(c + lr) * SK + kc + lq]);
                bf[nf][1] = f2tf(Kb[(c + lr) * SK + kc + lq + 4]);
            }
            #pragma unroll
            for (int mf = 0; mf < 2; mf++)
                #pragma unroll
                for (int nf = 0; nf < 2; nf++)
                    mma8(sacc[mf][nf], a[mf], bf[nf]);
        }

        // issue K(kt+1), V(kt+1)
        if (kt < 31) {
            float* Kn = Kf + ((kt + 1) & 1) * 64 * SK;
            const float* kg = Kbase + (size_t)(kc0 + 64 + kldr) * QKVW + kldc;
            cpa16(&Kn[kldr * SK + kldc],     kg);
            cpa16(&Kn[kldr * SK + kldc + 4], kg + 4);
            CP_COMMIT();
            float* Vn = Vf + ((kt + 1) & 1) * 64 * SV;
            const float* vg = Vbase + (size_t)(kc0 + 64 + kldr) * QKVW + kldc;
            cpa16(&Vn[kldr * SV + kldc],     vg);
            cpa16(&Vn[kldr * SV + kldc + 4], vg + 4);
            CP_COMMIT();
        }

        // ---- fold alibi + mask into sacc ----
        #pragma unroll
        for (int mf = 0; mf < 2; mf++) {
            #pragma unroll
            for (int nf = 0; nf < 2; nf++) {
                bool m0 = (mk[nf] & 0xFF) != 0;
                bool m1 = (mk[nf] >> 8) != 0;
                sacc[mf][nf][0] = m0 ? -1e30f : sacc[mf][nf][0] + al[mf][nf][0].x;
                sacc[mf][nf][1] = m1 ? -1e30f : sacc[mf][nf][1] + al[mf][nf][0].y;
                sacc[mf][nf][2] = m0 ? -1e30f : sacc[mf][nf][2] + al[mf][nf][1].x;
                sacc[mf][nf][3] = m1 ? -1e30f : sacc[mf][nf][3] + al[mf][nf][1].y;
            }
        }

        // ---- per-row tile max: quad shfl + cross-warp partials ----
        #pragma unroll
        for (int mf = 0; mf < 2; mf++) {
            #pragma unroll
            for (int hh = 0; hh < 2; hh++) {
                float pm = fmaxf(fmaxf(sacc[mf][0][hh*2], sacc[mf][0][hh*2+1]),
                                 fmaxf(sacc[mf][1][hh*2], sacc[mf][1][hh*2+1]));
                pm = fmaxf(pm, __shfl_xor_sync(0xffffffffu, pm, 1));
                pm = fmaxf(pm, __shfl_xor_sync(0xffffffffu, pm, 2));
                if (lq == 0) red[(rm + mf * 16 + lr + hh * 8) * 8 + wn] = pm;
            }
        }

        if (kt < 31) { CP_WAIT(2); } else { CP_WAIT(0); }  // V(kt) landed
        __syncthreads();   // S2: partial maxes + V visible

        // ---- softmax in registers; write tf32 probs + partial sums ----
        float fac[2][2];
        #pragma unroll
        for (int mf = 0; mf < 2; mf++) {
            #pragma unroll
            for (int hh = 0; hh < 2; hh++) {
                int r = rm + mf * 16 + lr + hh * 8;
                float rmx = fmaxf(fmaxf(red[r*8+0], red[r*8+1]),
                                  fmaxf(red[r*8+2], red[r*8+3]));
                float mnew = fmaxf(mrow_r[mf][hh], rmx);
                fac[mf][hh] = __expf(mrow_r[mf][hh] - mnew);
                mrow_r[mf][hh] = mnew;
                float p00 = __expf(sacc[mf][0][hh*2]   - mnew);
                float p01 = __expf(sacc[mf][0][hh*2+1] - mnew);
                float p10 = __expf(sacc[mf][1][hh*2]   - mnew);
                float p11 = __expf(sacc[mf][1][hh*2+1] - mnew);
                float part = (p00 + p01) + (p10 + p11);
                part += __shfl_xor_sync(0xffffffffu, part, 1);
                part += __shfl_xor_sync(0xffffffffu, part, 2);
                if (lq == 0) red[r * 8 + 4 + wn] = part;
                *(float2*)&Ss[r * SS + cn + 2 * lq] =
                    make_float2(__uint_as_float(f2tf(p00)), __uint_as_float(f2tf(p01)));
                *(float2*)&Ss[r * SS + cn + 8 + 2 * lq] =
                    make_float2(__uint_as_float(f2tf(p10)), __uint_as_float(f2tf(p11)));
                #pragma unroll
                for (int nf = 0; nf < 2; nf++) {
                    oacc[mf][nf][hh*2]   *= fac[mf][hh];
                    oacc[mf][nf][hh*2+1] *= fac[mf][hh];
                }
            }
        }
        __syncthreads();   // S3: probs + partial sums visible

        // ---- l update + O += P @ V ----
        #pragma unroll
        for (int mf = 0; mf < 2; mf++) {
            #pragma unroll
            for (int hh = 0; hh < 2; hh++) {
                int r = rm + mf * 16 + lr + hh * 8;
                float ssum = (red[r*8+4] + red[r*8+5]) + (red[r*8+6] + red[r*8+7]);
                lrow_r[mf][hh] = lrow_r[mf][hh] * fac[mf][hh] + ssum;
            }
        }
        const float* Vb = Vf + (kt & 1) * 64 * SV;
        #pragma unroll
        for (int kc = 0; kc < 64; kc += 8) {
            uint32_t a[2][4], bf[2][2];
            #pragma unroll
            for (int mf = 0; mf < 2; mf++) {
                int r = rm + mf * 16;
                a[mf][0] = __float_as_uint(Ss[(r + lr    ) * SS + kc + lq]);
                a[mf][1] = __float_as_uint(Ss[(r + lr + 8) * SS + kc + lq]);
                a[mf][2] = __float_as_uint(Ss[(r + lr    ) * SS + kc + lq + 4]);
                a[mf][3] = __float_as_uint(Ss[(r + lr + 8) * SS + kc + lq + 4]);
            }
            #pragma unroll
            for (int nf = 0; nf < 2; nf++) {
                int c = cn + nf * 8;
                bf[nf][0] = f2tf(Vb[(kc + lq    ) * SV + c + lr]);
                bf[nf][1] = f2tf(Vb[(kc + lq + 4) * SV + c + lr]);
            }
            #pragma unroll
            for (int mf = 0; mf < 2; mf++)
                #pragma unroll
                for (int nf = 0; nf < 2; nf++)
                    mma8(oacc[mf][nf], a[mf], bf[nf]);
        }
    }

    // ---- normalize, tf32-round, write [B,N,H,D] ----
    #pragma unroll
    for (int mf = 0; mf < 2; mf++) {
        int q = rm + mf * 16 + lr;
        float inv0 = 1.0f / lrow_r[mf][0];
        float inv1 = 1.0f / lrow_r[mf][1];
        #pragma unroll
        for (int nf = 0; nf < 2; nf++) {
            int c = cn + nf * 8 + 2 * lq;
            size_t o0 = ((size_t)(b * NN + q0 + q) * HH + h) * DD + c;
            size_t o1 = ((size_t)(b * NN + q0 + q + 8) * HH + h) * DD + c;
            *(uint2*)&g_attn[o0] = make_uint2(f2tf(oacc[mf][nf][0] * inv0),
                                              f2tf(oacc[mf][nf][1] * inv0));
            *(uint2*)&g_attn[o1] = make_uint2(f2tf(oacc[mf][nf][2] * inv1),
                                              f2tf(oacc[mf][nf][3] * inv1));
        }
    }
}

extern "C" void kernel_launch(void* const* d_in, const int* in_sizes, int n_in,
                              void* d_out, int out_size)
{
    const float* x      = nullptr;
    const void*  pmask  = nullptr;
    const float* alibi  = nullptr;
    const float* qkv_w  = nullptr;
    const float* qkv_b  = nullptr;
    const float* proj_w = nullptr;
    const float* proj_b = nullptr;
    for (int i = 0; i < n_in; i++) {
        switch (in_sizes[i]) {
            case 6291456:   x      = (const float*)d_in[i]; break;
            case 8192:      pmask  = d_in[i];               break;
            case 201326592: alibi  = (const float*)d_in[i]; break;
            case 1769472:   qkv_w  = (const float*)d_in[i]; break;
            case 2304:      qkv_b  = (const float*)d_in[i]; break;
            case 589824:    proj_w = (const float*)d_in[i]; break;
            case 768:       proj_b = (const float*)d_in[i]; break;
        }
    }
    float* out = (float*)d_out;

    cudaFuncSetAttribute(attn_kernel,
                         cudaFuncAttributeMaxDynamicSharedMemorySize, ATT_SM_BYTES);
    cudaFuncSetAttribute(gemm_tc<0>,
                         cudaFuncAttributeMaxDynamicSharedMemorySize, GEMM_SM_BYTES);
    cudaFuncSetAttribute(gemm_tc<1>,
                         cudaFuncAttributeMaxDynamicSharedMemorySize, GEMM_SM_BYTES);

    mask_conv_kernel<<<1, 1024>>>(pmask);
    conv_x_kernel<<<6144, 256>>>(x);

    // 1) qkv_w^T (tf32) ; QKV projection -> g_qkv
    transpose_k<<<dim3(QKVW / 32, CC / 32), dim3(32, 8)>>>(qkv_w, CC, QKVW);
    gemm_tc<0><<<dim3(QKVW / 128, (BB * NN) / 128), 256, GEMM_SM_BYTES>>>(
        qkv_b, nullptr, CC, QKVW);

    // 2) fused attention (128q tiles, 512 threads)
    attn_kernel<<<dim3(NN / 128, HH, BB), 512, ATT_SM_BYTES>>>(alibi);

    // 3) proj_w^T (tf32) ; output projection -> d_out
    transpose_k<<<dim3(CC / 32, CC / 32), dim3(32, 8)>>>(proj_w, CC, CC);
    gemm_tc<1><<<dim3(CC / 128, (BB * NN) / 128), 256, GEMM_SM_BYTES>>>(
        proj_b, out, CC, CC);
}